// round 7
// baseline (speedup 1.0000x reference)
#include <cuda_runtime.h>
#include <cuda_bf16.h>
#include <cstdint>

#define B_ROWS 16384
#define NDIM   4096
#define KDIM   784
#define TOPK   64
#define KPAD   2368        // 3*784 = 2352 padded to 2368 = 37*64
#define KCHUNKS 37         // KPAD / 64
#define KPADB  (KPAD * 2)  // row bytes of bf16 expanded arrays

// ---- scratch (static device globals; no allocations allowed) ----
__device__ __nv_bfloat16 g_X3[(size_t)B_ROWS * KPAD];   // 77.6 MB
__device__ __nv_bfloat16 g_W3[(size_t)NDIM * KPAD];     // 19.4 MB
__device__ float g_Wt[NDIM * KDIM];                     // fp32 W^T for decoder
__device__ int   g_cnt[B_ROWS];
__device__ int   g_idx[B_ROWS * TOPK];
__device__ float g_val[B_ROWS * TOPK];
__device__ int   g_total;

// ================= PTX helpers (baseline sm_80-level, valid on compute_103) ==
__device__ __forceinline__ uint32_t smem_to_u32(const void* p) {
    uint32_t a;
    asm("{ .reg .u64 t; cvta.to.shared.u64 t, %1; cvt.u32.u64 %0, t; }"
        : "=r"(a) : "l"(p));
    return a;
}
__device__ __forceinline__ void cp16(uint32_t dst, const void* src) {
    asm volatile("cp.async.cg.shared.global [%0], [%1], 16;" :: "r"(dst), "l"(src));
}
#define CP_COMMIT() asm volatile("cp.async.commit_group;" ::: "memory")
#define CP_WAIT1()  asm volatile("cp.async.wait_group 1;" ::: "memory")
#define CP_WAIT0()  asm volatile("cp.async.wait_group 0;" ::: "memory")

__device__ __forceinline__ void ldsm_x4(uint32_t* r, uint32_t addr) {
    asm volatile("ldmatrix.sync.aligned.m8n8.x4.shared.b16 {%0,%1,%2,%3}, [%4];"
                 : "=r"(r[0]), "=r"(r[1]), "=r"(r[2]), "=r"(r[3]) : "r"(addr));
}
__device__ __forceinline__ void mma_bf16(float* c, const uint32_t* a,
                                         uint32_t b0, uint32_t b1) {
    asm volatile(
        "mma.sync.aligned.m16n8k16.row.col.f32.bf16.bf16.f32 "
        "{%0,%1,%2,%3}, {%4,%5,%6,%7}, {%8,%9}, {%0,%1,%2,%3};"
        : "+f"(c[0]), "+f"(c[1]), "+f"(c[2]), "+f"(c[3])
        : "r"(a[0]), "r"(a[1]), "r"(a[2]), "r"(a[3]), "r"(b0), "r"(b1));
}

// ================= bf16 2-limb split =================
__device__ __forceinline__ void split2(float a, __nv_bfloat16& h0, __nv_bfloat16& h1) {
    h0 = __float2bfloat16(a);
    h1 = __float2bfloat16(a - __bfloat162float(h0));
}

// ---------------- P0: split x -> X3 ----------------
// per k: X3[m, 3k + {0,1,2}] = [a0, a1, a0]   (pairs with W pattern [b0, b0, b1])
// process k in pairs -> 3 aligned uint32 stores
__global__ __launch_bounds__(256) void split_x(const float* __restrict__ x) {
    int idx = blockIdx.x * 256 + threadIdx.x;
    int m = idx / 394;
    int u = idx - m * 394;
    if (m >= B_ROWS) return;
    char* rowp = (char*)g_X3 + (size_t)m * KPADB;
    if (u < 392) {
        int k = 2 * u;
        float2 xv = *(const float2*)(x + (size_t)m * KDIM + k);
        __nv_bfloat16 a0, a1, c0, c1;
        split2(xv.x, a0, a1);
        split2(xv.y, c0, c1);
        __nv_bfloat162* p = (__nv_bfloat162*)(rowp + 12 * u);
        p[0] = __halves2bfloat162(a0, a1);   // 3k+0, 3k+1
        p[1] = __halves2bfloat162(a0, c0);   // 3k+2, 3k+3
        p[2] = __halves2bfloat162(c1, c0);   // 3k+4, 3k+5
    } else {
        *(uint4*)(rowp + 4704 + (u - 392) * 16) = make_uint4(0, 0, 0, 0);
    }
}

// ---------------- P1: split W -> W3 (transposed, K-major) ----------------
// per k: W3[n, 3k + {0,1,2}] = [b0, b0, b1]
__global__ __launch_bounds__(256) void split_w(const float* __restrict__ W) {
    int n = blockIdx.x * 256 + threadIdx.x;   // 0..4095
    int u = blockIdx.y;                        // 0..393
    char* rowp = (char*)g_W3 + (size_t)n * KPADB;
    if (u < 392) {
        int k = 2 * u;
        __nv_bfloat16 b0, b1, d0, d1;
        split2(W[(size_t)k * NDIM + n], b0, b1);
        split2(W[(size_t)(k + 1) * NDIM + n], d0, d1);
        __nv_bfloat162* p = (__nv_bfloat162*)(rowp + 12 * u);
        p[0] = __halves2bfloat162(b0, b0);   // 3k+0, 3k+1
        p[1] = __halves2bfloat162(b1, d0);   // 3k+2, 3k+3
        p[2] = __halves2bfloat162(d0, d1);   // 3k+4, 3k+5
    } else {
        *(uint4*)(rowp + 4704 + (u - 392) * 16) = make_uint4(0, 0, 0, 0);
    }
}

// ---------------- P2: fp32 transpose for decoder + zero counter ----------------
__global__ void transpose_kernel(const float* __restrict__ W) {
    __shared__ float tile[32][33];
    int m0 = blockIdx.x * 32;
    int d0 = blockIdx.y * 32;
    int tx = threadIdx.x, ty = threadIdx.y;   // 32 x 8
#pragma unroll
    for (int i = 0; i < 32; i += 8) {
        int d = d0 + ty + i;
        if (d < KDIM) tile[ty + i][tx] = W[(size_t)d * NDIM + m0 + tx];
    }
    __syncthreads();
#pragma unroll
    for (int i = 0; i < 32; i += 8) {
        int d = d0 + tx;
        if (d < KDIM) g_Wt[(size_t)(m0 + ty + i) * KDIM + d] = tile[tx][ty + i];
    }
    if (blockIdx.x == 0 && blockIdx.y == 0 && tx == 0 && ty == 0) g_total = 0;
}

// ---------------- K1: encoder GEMM via mma.sync (bf16, fp32 accum) ----------------
// enc[16384,4096] = X3[16384,KPAD] @ W3[4096,KPAD]^T + b1
// CTA tile 128x256, 8 warps (warp tile 64x64), BK=64, 2-stage cp.async pipeline.
// SMEM pitch 144B (9*16) -> ldmatrix 8-row groups hit distinct banks.
#define PITCH  144u
#define ASTG   (128u * PITCH)        // 18432
#define BSTG   (256u * PITCH)        // 36864
#define STG    (ASTG + BSTG)         // 55296
#define SMEM_GEMM (2 * STG)          // 110592

__device__ __forceinline__ void load_stage(uint32_t sA, const char* Ag,
                                           const char* Bg, int chunk, int tid) {
    const uint32_t sB = sA + ASTG;
    const char* ga = Ag + (size_t)chunk * 128;
#pragma unroll
    for (int l = 0; l < 4; l++) {
        int u = tid + 256 * l;
        int r = u >> 3, q = u & 7;
        cp16(sA + r * PITCH + q * 16, ga + (size_t)r * KPADB + q * 16);
    }
    const char* gb = Bg + (size_t)chunk * 128;
#pragma unroll
    for (int l = 0; l < 8; l++) {
        int u = tid + 256 * l;
        int r = u >> 3, q = u & 7;
        cp16(sB + r * PITCH + q * 16, gb + (size_t)r * KPADB + q * 16);
    }
}

__global__ __launch_bounds__(256, 1)
void encoder_mma(const float* __restrict__ b1, float* __restrict__ enc) {
    extern __shared__ char smraw[];
    const uint32_t smb = smem_to_u32(smraw);

    const int tid  = threadIdx.x;
    const int wid  = tid >> 5;
    const int lane = tid & 31;
    const int wm   = (wid & 1) * 64;     // warp m offset within 128
    const int wn   = (wid >> 1) * 64;    // warp n offset within 256
    const int m0   = blockIdx.y * 128;
    const int n0   = blockIdx.x * 256;

    const char* Ag = (const char*)(g_X3 + (size_t)m0 * KPAD);
    const char* Bg = (const char*)(g_W3 + (size_t)n0 * KPAD);

    float acc[128];
#pragma unroll
    for (int i = 0; i < 128; i++) acc[i] = 0.0f;

    // prologue: stage 0
    load_stage(smb, Ag, Bg, 0, tid);
    CP_COMMIT();

    // lane-dependent ldmatrix offsets (same mapping as validated round-5 kernel)
    const uint32_t a_row = (lane & 7) + 8 * ((lane >> 3) & 1);
    const uint32_t a_kof = ((lane >> 4) << 3);
    const uint32_t b_row = (lane & 7) + 8 * ((lane >> 4) & 1);
    const uint32_t b_kof = ((lane >> 3) & 1) << 3;

    for (int c = 0; c < KCHUNKS; c++) {
        if (c + 1 < KCHUNKS) {
            load_stage(smb + (uint32_t)((c + 1) & 1) * STG, Ag, Bg, c + 1, tid);
            CP_COMMIT();
            CP_WAIT1();
        } else {
            CP_WAIT0();
        }
        __syncthreads();

        const uint32_t sA = smb + (uint32_t)(c & 1) * STG;
        const uint32_t sB = sA + ASTG;
#pragma unroll
        for (int h = 0; h < 4; h++) {
            const uint32_t k0 = h * 16;
            uint32_t a[4][4];
#pragma unroll
            for (int mi = 0; mi < 4; mi++)
                ldsm_x4(a[mi], sA + (wm + 16 * mi + a_row) * PITCH + (k0 + a_kof) * 2);
#pragma unroll
            for (int nb = 0; nb < 4; nb++) {
                uint32_t b[4];
                ldsm_x4(b, sB + (wn + 16 * nb + b_row) * PITCH + (k0 + b_kof) * 2);
#pragma unroll
                for (int mi = 0; mi < 4; mi++) {
                    mma_bf16(acc + (mi * 8 + 2 * nb) * 4,     a[mi], b[0], b[1]);
                    mma_bf16(acc + (mi * 8 + 2 * nb + 1) * 4, a[mi], b[2], b[3]);
                }
            }
        }
        __syncthreads();   // all warps done reading before next overwrite
    }

    // epilogue: acc -> +bias -> enc (direct, float2 stores)
    const int rg = lane >> 2;          // row group 0..7
    const int cg = (lane & 3) * 2;     // col pair base
#pragma unroll
    for (int mi = 0; mi < 4; mi++) {
#pragma unroll
        for (int ni = 0; ni < 8; ni++) {
            const float* a4 = acc + (mi * 8 + ni) * 4;
            const int n = n0 + wn + 8 * ni + cg;
            const float2 bias = *(const float2*)(b1 + n);
            const int m = m0 + wm + 16 * mi + rg;
            float2 o0 = make_float2(a4[0] + bias.x, a4[1] + bias.y);
            float2 o1 = make_float2(a4[2] + bias.x, a4[3] + bias.y);
            *(float2*)(enc + (size_t)m * NDIM + n)       = o0;
            *(float2*)(enc + (size_t)(m + 8) * NDIM + n) = o1;
        }
    }
}

// ---------------- K2: top-K with fp32 boundary recompute ----------------
// Boundary candidates (|av-T| < MARGIN) recomputed with the EXACT round-1
// summation order (acc from 0, serial k, bias added last) -> measured 0 flips.
#define MARGIN 1e-4f

__global__ __launch_bounds__(256)
void topk_kernel(float* __restrict__ enc, float* __restrict__ res,
                 const float* __restrict__ x, const float* __restrict__ b1) {
    const int row = blockIdx.x;
    const int tid = threadIdx.x;
    float* er = enc + (size_t)row * NDIM;

    float v[16];
    unsigned int ab[16];
#pragma unroll
    for (int i = 0; i < 16; i++) {
        v[i]  = er[tid + 256 * i];
        ab[i] = __float_as_uint(v[i]) & 0x7fffffffu;
    }

    __shared__ int s_warp[8];
    __shared__ int s_total;
    __shared__ int s_slot;

    unsigned int T = 0;
    for (int pass = 0; pass < 2; pass++) {
        unsigned int lo = 0u, hi = 0x7f800000u;
        while (hi - lo > 1u) {
            unsigned int mid = lo + ((hi - lo) >> 1);
            int c = 0;
#pragma unroll
            for (int i = 0; i < 16; i++) c += (ab[i] >= mid);
#pragma unroll
            for (int o = 16; o; o >>= 1) c += __shfl_xor_sync(0xffffffffu, c, o);
            if ((tid & 31) == 0) s_warp[tid >> 5] = c;
            __syncthreads();
            if (tid == 0) {
                int t = 0;
#pragma unroll
                for (int w = 0; w < 8; w++) t += s_warp[w];
                s_total = t;
            }
            __syncthreads();
            if ((unsigned)s_total >= 65u) lo = mid; else hi = mid;
        }
        T = lo;

        if (pass == 0) {
            const float Tf = __uint_as_float(T);
            const float* xr = x + (size_t)row * KDIM;
#pragma unroll
            for (int i = 0; i < 16; i++) {
                float av = __uint_as_float(ab[i]);
                if (fabsf(av - Tf) < MARGIN) {
                    const int n = tid + 256 * i;
                    const float* wt = g_Wt + (size_t)n * KDIM;
                    float s = 0.0f;
                    for (int d = 0; d < KDIM; d++) s = fmaf(xr[d], wt[d], s);
                    s = s + b1[n];      // bias LAST, plain add (round-1 order)
                    v[i]  = s;
                    ab[i] = __float_as_uint(s) & 0x7fffffffu;
                    er[n] = s;          // keep enc output consistent
                }
            }
            __syncthreads();
        }
    }

    if (tid == 0) s_slot = 0;
    __syncthreads();

    float* rr = res + (size_t)row * NDIM;
    const int base = row * TOPK;
#pragma unroll
    for (int i = 0; i < 16; i++) {
        bool act = (ab[i] > T);
        rr[tid + 256 * i] = act ? v[i] : 0.0f;
        if (act) {
            int s = atomicAdd(&s_slot, 1);
            g_idx[base + s] = tid + 256 * i;
            g_val[base + s] = v[i];
        }
    }
    __syncthreads();
    if (tid == 0) {
        g_cnt[row] = s_slot;
        atomicAdd(&g_total, s_slot);
    }
}

// ---------------- K3: sparse decoder + nnz ----------------
__global__ __launch_bounds__(256)
void decoder_kernel(const float* __restrict__ b2, float* __restrict__ dec,
                    float* __restrict__ nnz_out) {
    const int row = blockIdx.x;
    const int tid = threadIdx.x;
    __shared__ int   s_idx[TOPK];
    __shared__ float s_val[TOPK];
    const int c = g_cnt[row];
    if (tid < TOPK && tid < c) {
        s_idx[tid] = g_idx[row * TOPK + tid];
        s_val[tid] = g_val[row * TOPK + tid];
    }
    __syncthreads();

    const int d0 = tid, d1 = tid + 256, d2 = tid + 512, d3 = tid + 768;
    const bool has3 = (d3 < KDIM);
    float a0 = b2[d0], a1 = b2[d1], a2 = b2[d2];
    float a3 = has3 ? b2[d3] : 0.0f;

#pragma unroll 4
    for (int j = 0; j < c; j++) {
        const float* wr = g_Wt + (size_t)s_idx[j] * KDIM;
        const float val = s_val[j];
        a0 = fmaf(val, wr[d0], a0);
        a1 = fmaf(val, wr[d1], a1);
        a2 = fmaf(val, wr[d2], a2);
        if (has3) a3 = fmaf(val, wr[d3], a3);
    }
    float* dr = dec + (size_t)row * KDIM;
    dr[d0] = a0; dr[d1] = a1; dr[d2] = a2;
    if (has3) dr[d3] = a3;

    if (row == 0 && tid == 0)
        nnz_out[0] = (float)g_total / (float)B_ROWS;
}

// ---------------- launch ----------------
extern "C" void kernel_launch(void* const* d_in, const int* in_sizes, int n_in,
                              void* d_out, int out_size) {
    const float* x  = (const float*)d_in[0];
    const float* W  = (const float*)d_in[1];
    const float* b1 = (const float*)d_in[2];
    const float* b2 = (const float*)d_in[3];

    float* out = (float*)d_out;
    float* enc = out;                                        // 16384*4096
    float* dec = out + (size_t)B_ROWS * NDIM;                // 16384*784
    float* nnz = dec + (size_t)B_ROWS * KDIM;                // 1
    float* res = nnz + 1;                                    // 16384*4096

    cudaFuncSetAttribute(encoder_mma, cudaFuncAttributeMaxDynamicSharedMemorySize,
                         SMEM_GEMM);

    transpose_kernel<<<dim3(NDIM / 32, (KDIM + 31) / 32), dim3(32, 8)>>>(W);
    split_x<<<(B_ROWS * 394 + 255) / 256, 256>>>(x);
    split_w<<<dim3(NDIM / 256, 394), 256>>>(W);
    encoder_mma<<<dim3(NDIM / 256, B_ROWS / 128), 256, SMEM_GEMM>>>(b1, enc);
    topk_kernel<<<B_ROWS, 256>>>(enc, res, x, b1);
    decoder_kernel<<<B_ROWS, 256>>>(b2, dec, nnz);
}

// round 8
// speedup vs baseline: 1.0073x; 1.0073x over previous
#include <cuda_runtime.h>
#include <cuda_bf16.h>
#include <cstdint>

#define B_ROWS 16384
#define NDIM   4096
#define KDIM   784
#define TOPK   64
#define KPAD   2368        // 3*784 = 2352 padded to 2368 = 37*64
#define KCHUNKS 37         // KPAD / 64
#define KPADB  (KPAD * 2)  // row bytes of bf16 expanded arrays

// ---- scratch (static device globals; no allocations allowed) ----
__device__ __nv_bfloat16 g_X3[(size_t)B_ROWS * KPAD];   // 77.6 MB
__device__ __nv_bfloat16 g_W3[(size_t)NDIM * KPAD];     // 19.4 MB
__device__ float g_Wt[NDIM * KDIM];                     // fp32 W^T for decoder
__device__ int   g_cnt[B_ROWS];
__device__ int   g_idx[B_ROWS * TOPK];
__device__ float g_val[B_ROWS * TOPK];
__device__ int   g_total;

// ================= PTX helpers (baseline sm_80-level, valid on compute_103) ==
__device__ __forceinline__ uint32_t smem_to_u32(const void* p) {
    uint32_t a;
    asm("{ .reg .u64 t; cvta.to.shared.u64 t, %1; cvt.u32.u64 %0, t; }"
        : "=r"(a) : "l"(p));
    return a;
}
__device__ __forceinline__ void cp16(uint32_t dst, const void* src) {
    asm volatile("cp.async.cg.shared.global [%0], [%1], 16;" :: "r"(dst), "l"(src));
}
#define CP_COMMIT() asm volatile("cp.async.commit_group;" ::: "memory")
#define CP_WAIT1()  asm volatile("cp.async.wait_group 1;" ::: "memory")
#define CP_WAIT0()  asm volatile("cp.async.wait_group 0;" ::: "memory")

__device__ __forceinline__ void ldsm_x4(uint32_t* r, uint32_t addr) {
    asm volatile("ldmatrix.sync.aligned.m8n8.x4.shared.b16 {%0,%1,%2,%3}, [%4];"
                 : "=r"(r[0]), "=r"(r[1]), "=r"(r[2]), "=r"(r[3]) : "r"(addr));
}
__device__ __forceinline__ void mma_bf16(float* c, const uint32_t* a,
                                         uint32_t b0, uint32_t b1) {
    asm volatile(
        "mma.sync.aligned.m16n8k16.row.col.f32.bf16.bf16.f32 "
        "{%0,%1,%2,%3}, {%4,%5,%6,%7}, {%8,%9}, {%0,%1,%2,%3};"
        : "+f"(c[0]), "+f"(c[1]), "+f"(c[2]), "+f"(c[3])
        : "r"(a[0]), "r"(a[1]), "r"(a[2]), "r"(a[3]), "r"(b0), "r"(b1));
}

// ================= bf16 2-limb split =================
__device__ __forceinline__ void split2(float a, __nv_bfloat16& h0, __nv_bfloat16& h1) {
    h0 = __float2bfloat16(a);
    h1 = __float2bfloat16(a - __bfloat162float(h0));
}

// ---------------- P0: split x -> X3 ----------------
// per k: X3[m, 3k + {0,1,2}] = [a0, a1, a0]   (pairs with W pattern [b0, b0, b1])
// process k in pairs -> 3 aligned uint32 stores
__global__ __launch_bounds__(256) void split_x(const float* __restrict__ x) {
    int idx = blockIdx.x * 256 + threadIdx.x;
    int m = idx / 394;
    int u = idx - m * 394;
    if (m >= B_ROWS) return;
    char* rowp = (char*)g_X3 + (size_t)m * KPADB;
    if (u < 392) {
        int k = 2 * u;
        float2 xv = *(const float2*)(x + (size_t)m * KDIM + k);
        __nv_bfloat16 a0, a1, c0, c1;
        split2(xv.x, a0, a1);
        split2(xv.y, c0, c1);
        __nv_bfloat162* p = (__nv_bfloat162*)(rowp + 12 * u);
        p[0] = __halves2bfloat162(a0, a1);   // 3k+0, 3k+1
        p[1] = __halves2bfloat162(a0, c0);   // 3k+2, 3k+3
        p[2] = __halves2bfloat162(c1, c0);   // 3k+4, 3k+5
    } else {
        *(uint4*)(rowp + 4704 + (u - 392) * 16) = make_uint4(0, 0, 0, 0);
    }
}

// ---------------- P1: split W -> W3 (transposed, K-major) ----------------
// per k: W3[n, 3k + {0,1,2}] = [b0, b0, b1]
__global__ __launch_bounds__(256) void split_w(const float* __restrict__ W) {
    int n = blockIdx.x * 256 + threadIdx.x;   // 0..4095
    int u = blockIdx.y;                        // 0..393
    char* rowp = (char*)g_W3 + (size_t)n * KPADB;
    if (u < 392) {
        int k = 2 * u;
        __nv_bfloat16 b0, b1, d0, d1;
        split2(W[(size_t)k * NDIM + n], b0, b1);
        split2(W[(size_t)(k + 1) * NDIM + n], d0, d1);
        __nv_bfloat162* p = (__nv_bfloat162*)(rowp + 12 * u);
        p[0] = __halves2bfloat162(b0, b0);   // 3k+0, 3k+1
        p[1] = __halves2bfloat162(b1, d0);   // 3k+2, 3k+3
        p[2] = __halves2bfloat162(d0, d1);   // 3k+4, 3k+5
    } else {
        *(uint4*)(rowp + 4704 + (u - 392) * 16) = make_uint4(0, 0, 0, 0);
    }
}

// ---------------- P2: fp32 transpose for decoder + zero counter ----------------
__global__ void transpose_kernel(const float* __restrict__ W) {
    __shared__ float tile[32][33];
    int m0 = blockIdx.x * 32;
    int d0 = blockIdx.y * 32;
    int tx = threadIdx.x, ty = threadIdx.y;   // 32 x 8
#pragma unroll
    for (int i = 0; i < 32; i += 8) {
        int d = d0 + ty + i;
        if (d < KDIM) tile[ty + i][tx] = W[(size_t)d * NDIM + m0 + tx];
    }
    __syncthreads();
#pragma unroll
    for (int i = 0; i < 32; i += 8) {
        int d = d0 + tx;
        if (d < KDIM) g_Wt[(size_t)(m0 + ty + i) * KDIM + d] = tile[tx][ty + i];
    }
    if (blockIdx.x == 0 && blockIdx.y == 0 && tx == 0 && ty == 0) g_total = 0;
}

// ---------------- K1: encoder GEMM via mma.sync (bf16, fp32 accum) ----------------
// enc[16384,4096] = X3[16384,KPAD] @ W3[4096,KPAD]^T + b1
// CTA tile 128x256, 8 warps (warp tile 64x64), BK=64, 2-stage cp.async pipeline.
// SMEM pitch 144B (9*16) -> ldmatrix 8-row groups hit distinct banks.
#define PITCH  144u
#define ASTG   (128u * PITCH)        // 18432
#define BSTG   (256u * PITCH)        // 36864
#define STG    (ASTG + BSTG)         // 55296
#define SMEM_GEMM (2 * STG)          // 110592

__device__ __forceinline__ void load_stage(uint32_t sA, const char* Ag,
                                           const char* Bg, int chunk, int tid) {
    const uint32_t sB = sA + ASTG;
    const char* ga = Ag + (size_t)chunk * 128;
#pragma unroll
    for (int l = 0; l < 4; l++) {
        int u = tid + 256 * l;
        int r = u >> 3, q = u & 7;
        cp16(sA + r * PITCH + q * 16, ga + (size_t)r * KPADB + q * 16);
    }
    const char* gb = Bg + (size_t)chunk * 128;
#pragma unroll
    for (int l = 0; l < 8; l++) {
        int u = tid + 256 * l;
        int r = u >> 3, q = u & 7;
        cp16(sB + r * PITCH + q * 16, gb + (size_t)r * KPADB + q * 16);
    }
}

__global__ __launch_bounds__(256, 1)
void encoder_mma(const float* __restrict__ b1, float* __restrict__ enc) {
    extern __shared__ char smraw[];
    const uint32_t smb = smem_to_u32(smraw);

    const int tid  = threadIdx.x;
    const int wid  = tid >> 5;
    const int lane = tid & 31;
    const int wm   = (wid & 1) * 64;     // warp m offset within 128
    const int wn   = (wid >> 1) * 64;    // warp n offset within 256
    const int m0   = blockIdx.y * 128;
    const int n0   = blockIdx.x * 256;

    const char* Ag = (const char*)(g_X3 + (size_t)m0 * KPAD);
    const char* Bg = (const char*)(g_W3 + (size_t)n0 * KPAD);

    float acc[128];
#pragma unroll
    for (int i = 0; i < 128; i++) acc[i] = 0.0f;

    // prologue: stage 0
    load_stage(smb, Ag, Bg, 0, tid);
    CP_COMMIT();

    // lane-dependent ldmatrix offsets (same mapping as validated round-5 kernel)
    const uint32_t a_row = (lane & 7) + 8 * ((lane >> 3) & 1);
    const uint32_t a_kof = ((lane >> 4) << 3);
    const uint32_t b_row = (lane & 7) + 8 * ((lane >> 4) & 1);
    const uint32_t b_kof = ((lane >> 3) & 1) << 3;

    for (int c = 0; c < KCHUNKS; c++) {
        if (c + 1 < KCHUNKS) {
            load_stage(smb + (uint32_t)((c + 1) & 1) * STG, Ag, Bg, c + 1, tid);
            CP_COMMIT();
            CP_WAIT1();
        } else {
            CP_WAIT0();
        }
        __syncthreads();

        const uint32_t sA = smb + (uint32_t)(c & 1) * STG;
        const uint32_t sB = sA + ASTG;
#pragma unroll
        for (int h = 0; h < 4; h++) {
            const uint32_t k0 = h * 16;
            uint32_t a[4][4];
#pragma unroll
            for (int mi = 0; mi < 4; mi++)
                ldsm_x4(a[mi], sA + (wm + 16 * mi + a_row) * PITCH + (k0 + a_kof) * 2);
#pragma unroll
            for (int nb = 0; nb < 4; nb++) {
                uint32_t b[4];
                ldsm_x4(b, sB + (wn + 16 * nb + b_row) * PITCH + (k0 + b_kof) * 2);
#pragma unroll
                for (int mi = 0; mi < 4; mi++) {
                    mma_bf16(acc + (mi * 8 + 2 * nb) * 4,     a[mi], b[0], b[1]);
                    mma_bf16(acc + (mi * 8 + 2 * nb + 1) * 4, a[mi], b[2], b[3]);
                }
            }
        }
        __syncthreads();   // all warps done reading before next overwrite
    }

    // epilogue: acc -> +bias -> enc (direct, float2 stores)
    const int rg = lane >> 2;          // row group 0..7
    const int cg = (lane & 3) * 2;     // col pair base
#pragma unroll
    for (int mi = 0; mi < 4; mi++) {
#pragma unroll
        for (int ni = 0; ni < 8; ni++) {
            const float* a4 = acc + (mi * 8 + ni) * 4;
            const int n = n0 + wn + 8 * ni + cg;
            const float2 bias = *(const float2*)(b1 + n);
            const int m = m0 + wm + 16 * mi + rg;
            float2 o0 = make_float2(a4[0] + bias.x, a4[1] + bias.y);
            float2 o1 = make_float2(a4[2] + bias.x, a4[3] + bias.y);
            *(float2*)(enc + (size_t)m * NDIM + n)       = o0;
            *(float2*)(enc + (size_t)(m + 8) * NDIM + n) = o1;
        }
    }
}

// ---------------- K2: top-K with fp32 boundary recompute ----------------
// Boundary candidates (|av-T| < MARGIN) recomputed with the EXACT round-1
// summation order (acc from 0, serial k, bias added last) -> measured 0 flips.
#define MARGIN 1e-4f

__global__ __launch_bounds__(256)
void topk_kernel(float* __restrict__ enc, float* __restrict__ res,
                 const float* __restrict__ x, const float* __restrict__ b1) {
    const int row = blockIdx.x;
    const int tid = threadIdx.x;
    float* er = enc + (size_t)row * NDIM;

    float v[16];
    unsigned int ab[16];
#pragma unroll
    for (int i = 0; i < 16; i++) {
        v[i]  = er[tid + 256 * i];
        ab[i] = __float_as_uint(v[i]) & 0x7fffffffu;
    }

    __shared__ int s_warp[8];
    __shared__ int s_total;
    __shared__ int s_slot;

    unsigned int T = 0;
    for (int pass = 0; pass < 2; pass++) {
        unsigned int lo = 0u, hi = 0x7f800000u;
        while (hi - lo > 1u) {
            unsigned int mid = lo + ((hi - lo) >> 1);
            int c = 0;
#pragma unroll
            for (int i = 0; i < 16; i++) c += (ab[i] >= mid);
#pragma unroll
            for (int o = 16; o; o >>= 1) c += __shfl_xor_sync(0xffffffffu, c, o);
            if ((tid & 31) == 0) s_warp[tid >> 5] = c;
            __syncthreads();
            if (tid == 0) {
                int t = 0;
#pragma unroll
                for (int w = 0; w < 8; w++) t += s_warp[w];
                s_total = t;
            }
            __syncthreads();
            if ((unsigned)s_total >= 65u) lo = mid; else hi = mid;
        }
        T = lo;

        if (pass == 0) {
            const float Tf = __uint_as_float(T);
            const float* xr = x + (size_t)row * KDIM;
#pragma unroll
            for (int i = 0; i < 16; i++) {
                float av = __uint_as_float(ab[i]);
                if (fabsf(av - Tf) < MARGIN) {
                    const int n = tid + 256 * i;
                    const float* wt = g_Wt + (size_t)n * KDIM;
                    float s = 0.0f;
                    for (int d = 0; d < KDIM; d++) s = fmaf(xr[d], wt[d], s);
                    s = s + b1[n];      // bias LAST, plain add (round-1 order)
                    v[i]  = s;
                    ab[i] = __float_as_uint(s) & 0x7fffffffu;
                    er[n] = s;          // keep enc output consistent
                }
            }
            __syncthreads();
        }
    }

    if (tid == 0) s_slot = 0;
    __syncthreads();

    float* rr = res + (size_t)row * NDIM;
    const int base = row * TOPK;
#pragma unroll
    for (int i = 0; i < 16; i++) {
        bool act = (ab[i] > T);
        rr[tid + 256 * i] = act ? v[i] : 0.0f;
        if (act) {
            int s = atomicAdd(&s_slot, 1);
            g_idx[base + s] = tid + 256 * i;
            g_val[base + s] = v[i];
        }
    }
    __syncthreads();
    if (tid == 0) {
        g_cnt[row] = s_slot;
        atomicAdd(&g_total, s_slot);
    }
}

// ---------------- K3: sparse decoder + nnz ----------------
__global__ __launch_bounds__(256)
void decoder_kernel(const float* __restrict__ b2, float* __restrict__ dec,
                    float* __restrict__ nnz_out) {
    const int row = blockIdx.x;
    const int tid = threadIdx.x;
    __shared__ int   s_idx[TOPK];
    __shared__ float s_val[TOPK];
    const int c = g_cnt[row];
    if (tid < TOPK && tid < c) {
        s_idx[tid] = g_idx[row * TOPK + tid];
        s_val[tid] = g_val[row * TOPK + tid];
    }
    __syncthreads();

    const int d0 = tid, d1 = tid + 256, d2 = tid + 512, d3 = tid + 768;
    const bool has3 = (d3 < KDIM);
    float a0 = b2[d0], a1 = b2[d1], a2 = b2[d2];
    float a3 = has3 ? b2[d3] : 0.0f;

#pragma unroll 4
    for (int j = 0; j < c; j++) {
        const float* wr = g_Wt + (size_t)s_idx[j] * KDIM;
        const float val = s_val[j];
        a0 = fmaf(val, wr[d0], a0);
        a1 = fmaf(val, wr[d1], a1);
        a2 = fmaf(val, wr[d2], a2);
        if (has3) a3 = fmaf(val, wr[d3], a3);
    }
    float* dr = dec + (size_t)row * KDIM;
    dr[d0] = a0; dr[d1] = a1; dr[d2] = a2;
    if (has3) dr[d3] = a3;

    if (row == 0 && tid == 0)
        nnz_out[0] = (float)g_total / (float)B_ROWS;
}

// ---------------- launch ----------------
extern "C" void kernel_launch(void* const* d_in, const int* in_sizes, int n_in,
                              void* d_out, int out_size) {
    const float* x  = (const float*)d_in[0];
    const float* W  = (const float*)d_in[1];
    const float* b1 = (const float*)d_in[2];
    const float* b2 = (const float*)d_in[3];

    float* out = (float*)d_out;
    float* enc = out;                                        // 16384*4096
    float* dec = out + (size_t)B_ROWS * NDIM;                // 16384*784
    float* nnz = dec + (size_t)B_ROWS * KDIM;                // 1
    float* res = nnz + 1;                                    // 16384*4096

    cudaFuncSetAttribute(encoder_mma, cudaFuncAttributeMaxDynamicSharedMemorySize,
                         SMEM_GEMM);

    transpose_kernel<<<dim3(NDIM / 32, (KDIM + 31) / 32), dim3(32, 8)>>>(W);
    split_x<<<(B_ROWS * 394 + 255) / 256, 256>>>(x);
    split_w<<<dim3(NDIM / 256, 394), 256>>>(W);
    encoder_mma<<<dim3(NDIM / 256, B_ROWS / 128), 256, SMEM_GEMM>>>(b1, enc);
    topk_kernel<<<B_ROWS, 256>>>(enc, res, x, b1);
    decoder_kernel<<<B_ROWS, 256>>>(b2, dec, nnz);
}

// round 9
// speedup vs baseline: 1.2099x; 1.2011x over previous
#include <cuda_runtime.h>
#include <cuda_bf16.h>
#include <cstdint>

#define B_ROWS 16384
#define NDIM   4096
#define KDIM   784
#define TOPK   64
#define KPAD   2368        // 3*784 = 2352 padded to 2368 = 37*64
#define KCHUNKS 37         // KPAD / 64
#define KPADB  (KPAD * 2)  // row bytes of bf16 expanded arrays

// ---- scratch (static device globals; no allocations allowed) ----
__device__ __nv_bfloat16 g_X3[(size_t)B_ROWS * KPAD];   // 77.6 MB
__device__ __nv_bfloat16 g_W3[(size_t)NDIM * KPAD];     // 19.4 MB
__device__ float g_Wt[NDIM * KDIM];                     // fp32 W^T for decoder
__device__ int   g_cnt[B_ROWS];
__device__ int   g_idx[B_ROWS * TOPK];
__device__ float g_val[B_ROWS * TOPK];
__device__ int   g_total;

// ================= PTX helpers (baseline sm_80-level, valid on compute_103) ==
__device__ __forceinline__ uint32_t smem_to_u32(const void* p) {
    uint32_t a;
    asm("{ .reg .u64 t; cvta.to.shared.u64 t, %1; cvt.u32.u64 %0, t; }"
        : "=r"(a) : "l"(p));
    return a;
}
__device__ __forceinline__ void cp16(uint32_t dst, const void* src) {
    asm volatile("cp.async.cg.shared.global [%0], [%1], 16;" :: "r"(dst), "l"(src));
}
#define CP_COMMIT() asm volatile("cp.async.commit_group;" ::: "memory")
#define CP_WAIT1()  asm volatile("cp.async.wait_group 1;" ::: "memory")
#define CP_WAIT0()  asm volatile("cp.async.wait_group 0;" ::: "memory")

__device__ __forceinline__ void ldsm_x4(uint32_t* r, uint32_t addr) {
    asm volatile("ldmatrix.sync.aligned.m8n8.x4.shared.b16 {%0,%1,%2,%3}, [%4];"
                 : "=r"(r[0]), "=r"(r[1]), "=r"(r[2]), "=r"(r[3]) : "r"(addr));
}
__device__ __forceinline__ void mma_bf16(float* c, const uint32_t* a,
                                         uint32_t b0, uint32_t b1) {
    asm volatile(
        "mma.sync.aligned.m16n8k16.row.col.f32.bf16.bf16.f32 "
        "{%0,%1,%2,%3}, {%4,%5,%6,%7}, {%8,%9}, {%0,%1,%2,%3};"
        : "+f"(c[0]), "+f"(c[1]), "+f"(c[2]), "+f"(c[3])
        : "r"(a[0]), "r"(a[1]), "r"(a[2]), "r"(a[3]), "r"(b0), "r"(b1));
}

// ================= bf16 2-limb split =================
__device__ __forceinline__ void split2(float a, __nv_bfloat16& h0, __nv_bfloat16& h1) {
    h0 = __float2bfloat16(a);
    h1 = __float2bfloat16(a - __bfloat162float(h0));
}

// ---------------- P0: split x -> X3 ----------------
__global__ __launch_bounds__(256) void split_x(const float* __restrict__ x) {
    int idx = blockIdx.x * 256 + threadIdx.x;
    int m = idx / 394;
    int u = idx - m * 394;
    if (m >= B_ROWS) return;
    char* rowp = (char*)g_X3 + (size_t)m * KPADB;
    if (u < 392) {
        int k = 2 * u;
        float2 xv = *(const float2*)(x + (size_t)m * KDIM + k);
        __nv_bfloat16 a0, a1, c0, c1;
        split2(xv.x, a0, a1);
        split2(xv.y, c0, c1);
        __nv_bfloat162* p = (__nv_bfloat162*)(rowp + 12 * u);
        p[0] = __halves2bfloat162(a0, a1);
        p[1] = __halves2bfloat162(a0, c0);
        p[2] = __halves2bfloat162(c1, c0);
    } else {
        *(uint4*)(rowp + 4704 + (u - 392) * 16) = make_uint4(0, 0, 0, 0);
    }
}

// ---------------- P1: split W -> W3 (transposed, K-major) ----------------
__global__ __launch_bounds__(256) void split_w(const float* __restrict__ W) {
    int n = blockIdx.x * 256 + threadIdx.x;
    int u = blockIdx.y;
    char* rowp = (char*)g_W3 + (size_t)n * KPADB;
    if (u < 392) {
        int k = 2 * u;
        __nv_bfloat16 b0, b1, d0, d1;
        split2(W[(size_t)k * NDIM + n], b0, b1);
        split2(W[(size_t)(k + 1) * NDIM + n], d0, d1);
        __nv_bfloat162* p = (__nv_bfloat162*)(rowp + 12 * u);
        p[0] = __halves2bfloat162(b0, b0);
        p[1] = __halves2bfloat162(b1, d0);
        p[2] = __halves2bfloat162(d0, d1);
    } else {
        *(uint4*)(rowp + 4704 + (u - 392) * 16) = make_uint4(0, 0, 0, 0);
    }
}

// ---------------- P2: fp32 transpose for decoder + zero counter ----------------
__global__ void transpose_kernel(const float* __restrict__ W) {
    __shared__ float tile[32][33];
    int m0 = blockIdx.x * 32;
    int d0 = blockIdx.y * 32;
    int tx = threadIdx.x, ty = threadIdx.y;
#pragma unroll
    for (int i = 0; i < 32; i += 8) {
        int d = d0 + ty + i;
        if (d < KDIM) tile[ty + i][tx] = W[(size_t)d * NDIM + m0 + tx];
    }
    __syncthreads();
#pragma unroll
    for (int i = 0; i < 32; i += 8) {
        int d = d0 + tx;
        if (d < KDIM) g_Wt[(size_t)(m0 + ty + i) * KDIM + d] = tile[tx][ty + i];
    }
    if (blockIdx.x == 0 && blockIdx.y == 0 && tx == 0 && ty == 0) g_total = 0;
}

// ---------------- K1: encoder GEMM via mma.sync (bf16, fp32 accum) ----------------
// CTA tile 128x256, 512 threads / 16 warps (warp tile 32x64), BK=64,
// 3-stage cp.async pipeline with ONE __syncthreads per chunk. pitch 144B.
#define PITCH  144u
#define ASTG   (128u * PITCH)        // 18432
#define BSTG   (256u * PITCH)        // 36864
#define STG    (ASTG + BSTG)         // 55296
#define SMEM_GEMM (3 * STG)          // 165888

__device__ __forceinline__ void load_stage(uint32_t sA, const char* Ag,
                                           const char* Bg, int chunk, int tid) {
    const uint32_t sB = sA + ASTG;
    const char* ga = Ag + (size_t)chunk * 128;
#pragma unroll
    for (int l = 0; l < 2; l++) {
        int u = tid + 512 * l;
        int r = u >> 3, q = u & 7;
        cp16(sA + r * PITCH + q * 16, ga + (size_t)r * KPADB + q * 16);
    }
    const char* gb = Bg + (size_t)chunk * 128;
#pragma unroll
    for (int l = 0; l < 4; l++) {
        int u = tid + 512 * l;
        int r = u >> 3, q = u & 7;
        cp16(sB + r * PITCH + q * 16, gb + (size_t)r * KPADB + q * 16);
    }
}

__global__ __launch_bounds__(512, 1)
void encoder_mma(const float* __restrict__ b1, float* __restrict__ enc) {
    extern __shared__ char smraw[];
    const uint32_t smb = smem_to_u32(smraw);

    const int tid  = threadIdx.x;
    const int wid  = tid >> 5;
    const int lane = tid & 31;
    const int wm   = (wid & 3) * 32;     // warp m offset within 128
    const int wn   = (wid >> 2) * 64;    // warp n offset within 256
    const int m0   = blockIdx.y * 128;
    const int n0   = blockIdx.x * 256;

    const char* Ag = (const char*)(g_X3 + (size_t)m0 * KPAD);
    const char* Bg = (const char*)(g_W3 + (size_t)n0 * KPAD);

    float acc[64];
#pragma unroll
    for (int i = 0; i < 64; i++) acc[i] = 0.0f;

    // prologue: stages 0, 1
    load_stage(smb, Ag, Bg, 0, tid);
    CP_COMMIT();
    load_stage(smb + STG, Ag, Bg, 1, tid);
    CP_COMMIT();

    // lane-dependent ldmatrix offsets (validated mapping)
    const uint32_t a_row = (lane & 7) + 8 * ((lane >> 3) & 1);
    const uint32_t a_kof = ((lane >> 4) << 3);
    const uint32_t b_row = (lane & 7) + 8 * ((lane >> 4) & 1);
    const uint32_t b_kof = ((lane >> 3) & 1) << 3;

    for (int c = 0; c < KCHUNKS; c++) {
        if (c < KCHUNKS - 1) { CP_WAIT1(); } else { CP_WAIT0(); }
        __syncthreads();     // chunk c visible to all; buf[(c+2)%3] free to refill
        if (c + 2 < KCHUNKS) {
            load_stage(smb + (uint32_t)((c + 2) % 3) * STG, Ag, Bg, c + 2, tid);
            CP_COMMIT();
        }

        const uint32_t sA = smb + (uint32_t)(c % 3) * STG;
        const uint32_t sB = sA + ASTG;
#pragma unroll
        for (int h = 0; h < 4; h++) {
            const uint32_t k0 = h * 16;
            uint32_t a[2][4];
#pragma unroll
            for (int mi = 0; mi < 2; mi++)
                ldsm_x4(a[mi], sA + (wm + 16 * mi + a_row) * PITCH + (k0 + a_kof) * 2);
#pragma unroll
            for (int nb = 0; nb < 4; nb++) {
                uint32_t b[4];
                ldsm_x4(b, sB + (wn + 16 * nb + b_row) * PITCH + (k0 + b_kof) * 2);
#pragma unroll
                for (int mi = 0; mi < 2; mi++) {
                    mma_bf16(acc + (mi * 8 + 2 * nb) * 4,     a[mi], b[0], b[1]);
                    mma_bf16(acc + (mi * 8 + 2 * nb + 1) * 4, a[mi], b[2], b[3]);
                }
            }
        }
    }

    // epilogue: acc -> +bias -> enc
    const int rg = lane >> 2;
    const int cg = (lane & 3) * 2;
#pragma unroll
    for (int mi = 0; mi < 2; mi++) {
#pragma unroll
        for (int ni = 0; ni < 8; ni++) {
            const float* a4 = acc + (mi * 8 + ni) * 4;
            const int n = n0 + wn + 8 * ni + cg;
            const float2 bias = *(const float2*)(b1 + n);
            const int m = m0 + wm + 16 * mi + rg;
            float2 o0 = make_float2(a4[0] + bias.x, a4[1] + bias.y);
            float2 o1 = make_float2(a4[2] + bias.x, a4[3] + bias.y);
            *(float2*)(enc + (size_t)m * NDIM + n)       = o0;
            *(float2*)(enc + (size_t)(m + 8) * NDIM + n) = o1;
        }
    }
}

// ---------------- K2: top-K via exact radix-256 select + boundary recompute ----
#define MARGIN 1e-4f

__global__ __launch_bounds__(256)
void topk_kernel(float* __restrict__ enc, float* __restrict__ res,
                 const float* __restrict__ x, const float* __restrict__ b1) {
    const int row = blockIdx.x;
    const int tid = threadIdx.x;
    const int lane = tid & 31;
    const int wid  = tid >> 5;
    float* er = enc + (size_t)row * NDIM;

    float v[16];
    unsigned ab[16];
#pragma unroll
    for (int i = 0; i < 16; i++) {
        v[i]  = er[tid + 256 * i];
        ab[i] = __float_as_uint(v[i]) & 0x7fffffffu;
    }

    __shared__ unsigned hist[256];
    __shared__ unsigned s_pref, s_want;
    __shared__ int s_slot;

    unsigned T = 0;
    for (int pass = 0; pass < 2; pass++) {
        unsigned prefix = 0, want = 65;
#pragma unroll
        for (int sh = 24; sh >= 0; sh -= 8) {
            hist[tid] = 0;
            __syncthreads();
            const unsigned mask = (sh == 24) ? 0u : (0xFFFFFFFFu << (sh + 8));
#pragma unroll
            for (int i = 0; i < 16; i++)
                if ((ab[i] & mask) == prefix)
                    atomicAdd(&hist[(ab[i] >> sh) & 255u], 1u);
            __syncthreads();
            if (wid == 0) {
                unsigned part = 0;
#pragma unroll
                for (int j = 0; j < 8; j++) part += hist[lane * 8 + j];
                unsigned suf = part;
#pragma unroll
                for (int o = 1; o < 32; o <<= 1) {
                    unsigned t2 = __shfl_down_sync(0xffffffffu, suf, o);
                    if (lane + o < 32) suf += t2;
                }
                unsigned sufNext = __shfl_down_sync(0xffffffffu, suf, 1);
                if (lane == 31) sufNext = 0;
                unsigned bal = __ballot_sync(0xffffffffu, suf >= want);
                int L = 31 - __clz(bal);     // total >= 65 always, so bal != 0
                if (lane == L) {
                    unsigned cumAbove = sufNext;
                    int digit = 0;
                    for (int j = 7; j >= 0; j--) {
                        unsigned h = hist[L * 8 + j];
                        if (cumAbove + h >= want) { digit = L * 8 + j; break; }
                        cumAbove += h;
                    }
                    s_pref = prefix | ((unsigned)digit << sh);
                    s_want = want - cumAbove;
                }
            }
            __syncthreads();
            prefix = s_pref;
            want   = s_want;
        }
        T = prefix;   // exact bits of 65th-largest |value|

        if (pass == 0) {
            // recompute boundary candidates in fp32, round-1 summation order
            const float Tf = __uint_as_float(T);
            const float* xr = x + (size_t)row * KDIM;
#pragma unroll
            for (int i = 0; i < 16; i++) {
                if (fabsf(__uint_as_float(ab[i]) - Tf) < MARGIN) {
                    const int n = tid + 256 * i;
                    const float* wt = g_Wt + (size_t)n * KDIM;
                    float s = 0.0f;
                    for (int d = 0; d < KDIM; d++) s = fmaf(xr[d], wt[d], s);
                    s = s + b1[n];      // bias LAST, plain add (round-1 order)
                    v[i]  = s;
                    ab[i] = __float_as_uint(s) & 0x7fffffffu;
                    er[n] = s;
                }
            }
        }
    }

    if (tid == 0) s_slot = 0;
    __syncthreads();

    float* rr = res + (size_t)row * NDIM;
    const int base = row * TOPK;
#pragma unroll
    for (int i = 0; i < 16; i++) {
        bool act = (ab[i] > T);
        rr[tid + 256 * i] = act ? v[i] : 0.0f;
        if (act) {
            int s = atomicAdd(&s_slot, 1);
            g_idx[base + s] = tid + 256 * i;
            g_val[base + s] = v[i];
        }
    }
    __syncthreads();
    if (tid == 0) {
        g_cnt[row] = s_slot;
        atomicAdd(&g_total, s_slot);
    }
}

// ---------------- K3: sparse decoder + nnz ----------------
__global__ __launch_bounds__(256)
void decoder_kernel(const float* __restrict__ b2, float* __restrict__ dec,
                    float* __restrict__ nnz_out) {
    const int row = blockIdx.x;
    const int tid = threadIdx.x;
    __shared__ int   s_idx[TOPK];
    __shared__ float s_val[TOPK];
    const int c = g_cnt[row];
    if (tid < TOPK && tid < c) {
        s_idx[tid] = g_idx[row * TOPK + tid];
        s_val[tid] = g_val[row * TOPK + tid];
    }
    __syncthreads();

    const int d0 = tid, d1 = tid + 256, d2 = tid + 512, d3 = tid + 768;
    const bool has3 = (d3 < KDIM);
    float a0 = b2[d0], a1 = b2[d1], a2 = b2[d2];
    float a3 = has3 ? b2[d3] : 0.0f;

#pragma unroll 4
    for (int j = 0; j < c; j++) {
        const float* wr = g_Wt + (size_t)s_idx[j] * KDIM;
        const float val = s_val[j];
        a0 = fmaf(val, wr[d0], a0);
        a1 = fmaf(val, wr[d1], a1);
        a2 = fmaf(val, wr[d2], a2);
        if (has3) a3 = fmaf(val, wr[d3], a3);
    }
    float* dr = dec + (size_t)row * KDIM;
    dr[d0] = a0; dr[d1] = a1; dr[d2] = a2;
    if (has3) dr[d3] = a3;

    if (row == 0 && tid == 0)
        nnz_out[0] = (float)g_total / (float)B_ROWS;
}

// ---------------- launch ----------------
extern "C" void kernel_launch(void* const* d_in, const int* in_sizes, int n_in,
                              void* d_out, int out_size) {
    const float* x  = (const float*)d_in[0];
    const float* W  = (const float*)d_in[1];
    const float* b1 = (const float*)d_in[2];
    const float* b2 = (const float*)d_in[3];

    float* out = (float*)d_out;
    float* enc = out;                                        // 16384*4096
    float* dec = out + (size_t)B_ROWS * NDIM;                // 16384*784
    float* nnz = dec + (size_t)B_ROWS * KDIM;                // 1
    float* res = nnz + 1;                                    // 16384*4096

    cudaFuncSetAttribute(encoder_mma, cudaFuncAttributeMaxDynamicSharedMemorySize,
                         SMEM_GEMM);

    transpose_kernel<<<dim3(NDIM / 32, (KDIM + 31) / 32), dim3(32, 8)>>>(W);
    split_x<<<(B_ROWS * 394 + 255) / 256, 256>>>(x);
    split_w<<<dim3(NDIM / 256, 394), 256>>>(W);
    encoder_mma<<<dim3(NDIM / 256, B_ROWS / 128), 512, SMEM_GEMM>>>(b1, enc);
    topk_kernel<<<B_ROWS, 256>>>(enc, res, x, b1);
    decoder_kernel<<<B_ROWS, 256>>>(b2, dec, nnz);
}